// round 1
// baseline (speedup 1.0000x reference)
#include <cuda_runtime.h>
#include <math.h>

#define SEQ   4096
#define DM    768
#define NH    12
#define DH    64
#define QKVC  2304          // 3 * DM
#define SCALE 0.125f        // 1/sqrt(64)

// Scratch (allocations are forbidden; __device__ globals are the sanctioned path)
__device__ float g_qkv[SEQ * QKVC];   // [S, 3*DM]  (Q | K | V per row)
__device__ float g_attn[SEQ * DM];    // attention output, heads concatenated

// ---------------------------------------------------------------------------
// C[M,N] = A[M,K] @ B[N,K]^T + bias[N]
// BM=BN=64, BK=16, 128 threads, each thread computes 8x4 outputs.
// ---------------------------------------------------------------------------
__global__ __launch_bounds__(128) void gemm_nt_bias(
    const float* __restrict__ A, const float* __restrict__ B,
    const float* __restrict__ bias, float* __restrict__ C,
    int M, int N, int K)
{
    __shared__ float As[16][68];   // [k][m], pad 68 keeps float4 reads aligned+conflict-free
    __shared__ float Bs[16][68];   // [k][n]

    const int tid = threadIdx.x;
    const int tx  = tid & 15;      // 0..15 -> N direction
    const int ty  = tid >> 4;      // 0..7  -> M direction
    const int m0  = blockIdx.y * 64;
    const int n0  = blockIdx.x * 64;

    float acc[8][4];
#pragma unroll
    for (int i = 0; i < 8; i++)
#pragma unroll
        for (int j = 0; j < 4; j++) acc[i][j] = 0.f;

    for (int kt = 0; kt < K; kt += 16) {
#pragma unroll
        for (int q = 0; q < 2; q++) {
            int idx = q * 128 + tid;          // 0..255
            int row = idx >> 2;               // 0..63
            int c   = (idx & 3) << 2;         // 0,4,8,12
            float4 va = *(const float4*)(A + (size_t)(m0 + row) * K + kt + c);
            As[c + 0][row] = va.x; As[c + 1][row] = va.y;
            As[c + 2][row] = va.z; As[c + 3][row] = va.w;
            float4 vb = *(const float4*)(B + (size_t)(n0 + row) * K + kt + c);
            Bs[c + 0][row] = vb.x; Bs[c + 1][row] = vb.y;
            Bs[c + 2][row] = vb.z; Bs[c + 3][row] = vb.w;
        }
        __syncthreads();

#pragma unroll
        for (int kk = 0; kk < 16; kk++) {
            float4 a0 = *(const float4*)&As[kk][ty * 8];
            float4 a1 = *(const float4*)&As[kk][ty * 8 + 4];
            float4 b4 = *(const float4*)&Bs[kk][tx * 4];
            float a[8] = {a0.x, a0.y, a0.z, a0.w, a1.x, a1.y, a1.z, a1.w};
            float b[4] = {b4.x, b4.y, b4.z, b4.w};
#pragma unroll
            for (int i = 0; i < 8; i++)
#pragma unroll
                for (int j = 0; j < 4; j++)
                    acc[i][j] += a[i] * b[j];
        }
        __syncthreads();
    }

#pragma unroll
    for (int i = 0; i < 8; i++) {
        int r = m0 + ty * 8 + i;
        int c = n0 + tx * 4;
        float4 bv = *(const float4*)(bias + c);
        float4 o;
        o.x = acc[i][0] + bv.x;
        o.y = acc[i][1] + bv.y;
        o.z = acc[i][2] + bv.z;
        o.w = acc[i][3] + bv.w;
        *(float4*)(C + (size_t)r * N + c) = o;
    }
}

// ---------------------------------------------------------------------------
// Flash-style causal attention.
// grid = (32 q-tiles, 12 heads), 128 threads. 1 thread = 1 query row.
// Q row (64f) and O accumulator (64f) in registers; K/V tiles (32x64) in smem,
// read as broadcast float4 so the loop is FMA-pipe-bound.
// ---------------------------------------------------------------------------
__global__ __launch_bounds__(128) void attn_kernel()
{
    const int h   = blockIdx.y;
    const int qt  = (int)gridDim.x - 1 - (int)blockIdx.x;  // big tiles first (load balance)
    const int tid = threadIdx.x;
    const int qi  = qt * 128 + tid;

    __shared__ float Ks[32][64];
    __shared__ float Vs[32][64];

    // Q row, pre-scaled
    float4 q[16];
    const float* qp = g_qkv + (size_t)qi * QKVC + h * DH;
#pragma unroll
    for (int i = 0; i < 16; i++) {
        float4 v = *(const float4*)(qp + i * 4);
        q[i] = make_float4(v.x * SCALE, v.y * SCALE, v.z * SCALE, v.w * SCALE);
    }

    float4 o[16];
#pragma unroll
    for (int i = 0; i < 16; i++) o[i] = make_float4(0.f, 0.f, 0.f, 0.f);
    float m = -INFINITY, l = 0.f;

    const int kmax = (qt + 1) * 128;
    for (int k0 = 0; k0 < kmax; k0 += 32) {
        __syncthreads();
#pragma unroll
        for (int q2 = 0; q2 < 4; q2++) {
            int idx = q2 * 128 + tid;         // 0..511
            int r   = idx >> 4;               // 0..31
            int c   = (idx & 15) << 2;        // 0..60
            const float* base = g_qkv + (size_t)(k0 + r) * QKVC + DM + h * DH + c;
            *(float4*)&Ks[r][c] = *(const float4*)base;
            *(float4*)&Vs[r][c] = *(const float4*)(base + DM);
        }
        __syncthreads();

        // scores
        float s[32];
#pragma unroll
        for (int k = 0; k < 32; k++) {
            float acc = 0.f;
#pragma unroll
            for (int d = 0; d < 16; d++) {
                float4 kv = *(const float4*)&Ks[k][d * 4];
                acc += q[d].x * kv.x;
                acc += q[d].y * kv.y;
                acc += q[d].z * kv.z;
                acc += q[d].w * kv.w;
            }
            s[k] = (k0 + k <= qi) ? acc : -INFINITY;
        }

        // online softmax
        float tm = s[0];
#pragma unroll
        for (int k = 1; k < 32; k++) tm = fmaxf(tm, s[k]);
        float mn    = fmaxf(m, tm);
        float alpha = __expf(m - mn);         // m=-inf first iter -> 0
        float psum  = 0.f;
#pragma unroll
        for (int k = 0; k < 32; k++) {
            s[k] = __expf(s[k] - mn);         // -inf -> 0
            psum += s[k];
        }
        l = l * alpha + psum;
        m = mn;

        // O = O*alpha + P @ V
#pragma unroll
        for (int d = 0; d < 16; d++) {
            float4 ov = o[d];
            ov.x *= alpha; ov.y *= alpha; ov.z *= alpha; ov.w *= alpha;
#pragma unroll
            for (int k = 0; k < 32; k++) {
                float4 v = *(const float4*)&Vs[k][d * 4];
                ov.x += s[k] * v.x;
                ov.y += s[k] * v.y;
                ov.z += s[k] * v.z;
                ov.w += s[k] * v.w;
            }
            o[d] = ov;
        }
    }

    const float inv = 1.f / l;
    float* op = g_attn + (size_t)qi * DM + h * DH;
#pragma unroll
    for (int d = 0; d < 16; d++) {
        float4 r = make_float4(o[d].x * inv, o[d].y * inv, o[d].z * inv, o[d].w * inv);
        *(float4*)(op + d * 4) = r;
    }
}

// ---------------------------------------------------------------------------
extern "C" void kernel_launch(void* const* d_in, const int* in_sizes, int n_in,
                              void* d_out, int out_size)
{
    const float* x     = (const float*)d_in[0];
    const float* W_in  = (const float*)d_in[1];
    const float* b_in  = (const float*)d_in[2];
    const float* W_out = (const float*)d_in[3];
    const float* b_out = (const float*)d_in[4];
    float* out = (float*)d_out;

    float* qkv_p;  cudaGetSymbolAddress((void**)&qkv_p,  g_qkv);
    float* attn_p; cudaGetSymbolAddress((void**)&attn_p, g_attn);

    // 1) qkv = x @ W_in^T + b_in   -> g_qkv [4096, 2304]
    {
        dim3 grid(QKVC / 64, SEQ / 64);
        gemm_nt_bias<<<grid, 128>>>(x, W_in, b_in, qkv_p, SEQ, QKVC, DM);
    }
    // 2) causal multi-head attention -> g_attn [4096, 768]
    {
        dim3 grid(SEQ / 128, NH);
        attn_kernel<<<grid, 128>>>();
    }
    // 3) out = attn @ W_out^T + b_out -> d_out
    {
        dim3 grid(DM / 64, SEQ / 64);
        gemm_nt_bias<<<grid, 128>>>(attn_p, W_out, b_out, out, SEQ, DM, DM);
    }
}